// round 14
// baseline (speedup 1.0000x reference)
#include <cuda_runtime.h>
#include <stdint.h>

#define KTAPS 27
#define SELF_K 13        // (0,0,0) offset: pair_in == row, mask == 1 always
#define CCH 64
#define TILE 32          // rows per block (2 rows per thread)
#define THREADS 256
#define MAXN 1048576     // scratch capacity (rows)

#define F32_ONE   0x3F800000u

// Per-row packed info: {neighbor bits (bit13 unused), j0, j1, j2} where
// j0..j2 are pair_in indices of the first (ascending k) set neighbor taps.
__device__ uint4 g_info[MAXN];

// ---------------- mask -> {bits, j0..j2} precompute ----------------
// Inline width detection: all blocks read the SAME fixed words (self-tap row 0
// mask is always "one"; self-tap pair_in is arange) -> identical decision
// everywhere, deterministic, L1/L2-broadcast. No separate probe kernel.
__global__ __launch_bounds__(256)
void kbits(const void* __restrict__ maskp, const void* __restrict__ pinp, int n)
{
    const unsigned* m32 = (const unsigned*)maskp;
    const unsigned w = __ldg(m32 + (size_t)SELF_K * (size_t)n);
    int mk = 0;                                   // 0 = 4-byte mask elements
    if (w != 1u && w != F32_ONE) {
        const unsigned w2 = __ldg(m32 + ((size_t)SELF_K * (size_t)n) / 2);
        if ((w2 & 0xFFFFu) == 0x3F80u) mk = 1;    // 1 = 2-byte (bf16) mask
    }
    const int* p32 = (const int*)pinp;
    const bool pw4 = (__ldg(p32 + (size_t)SELF_K * (size_t)n + 1) == 1) &&
                     (__ldg(p32 + (size_t)SELF_K * (size_t)n + 2) == 2);

    const int row = blockIdx.x * 256 + threadIdx.x;
    if (row >= n) return;

    unsigned bits = 0u;
    if (mk == 0) {
        #pragma unroll
        for (int kk = 0; kk < 26; kk++) {
            const int k = kk + (kk >= SELF_K);
            if (__ldcs(m32 + (size_t)k * (size_t)n + row)) bits |= 1u << k;
        }
    } else {
        const unsigned short* m16 = (const unsigned short*)maskp;
        #pragma unroll
        for (int kk = 0; kk < 26; kk++) {
            const int k = kk + (kk >= SELF_K);
            if (__ldcs(m16 + (size_t)k * (size_t)n + row)) bits |= 1u << k;
        }
    }

    // Fetch pair_in for the first <=3 set neighbor taps (ascending k).
    // P(>3 neighbors) ~ 6e-4: overflow taps are read directly by the main
    // kernel (order preserved by ascending-k consumption there).
    unsigned j0 = 0, j1 = 0, j2 = 0;
    unsigned bb = bits;
    int cnt = 0;
    while (bb && cnt < 3) {
        const int k = __ffs(bb) - 1;
        bb &= bb - 1;
        const unsigned j = pw4
            ? (unsigned)__ldg(p32 + (size_t)k * (size_t)n + row)
            : (unsigned)__ldg((const long long*)pinp + (size_t)k * (size_t)n + row);
        if (cnt == 0) j0 = j; else if (cnt == 1) j1 = j; else j2 = j;
        cnt++;
    }
    g_info[row] = make_uint4(bits, j0, j1, j2);
}

// Per-row tap accumulation (ascending k; j0..j2 consumed in stored order).
__device__ __forceinline__ void row_taps(
    float4& acc, const uint4 info, int nn,
    const float* __restrict__ features, const float* __restrict__ weight,
    int c4, const int* __restrict__ p32, const void* __restrict__ pinp,
    bool pw4, int n)
{
    unsigned blo = info.x & ((1u << SELF_K) - 1u);
    unsigned bhi = info.x >> (SELF_K + 1);
    int cnt = 0;

    while (blo) {
        const int k = __ffs(blo) - 1;
        blo &= blo - 1;
        int j;
        if      (cnt == 0) j = (int)info.y;
        else if (cnt == 1) j = (int)info.z;
        else if (cnt == 2) j = (int)info.w;
        else j = pw4 ? __ldg(p32 + (size_t)k * (size_t)n + nn)
                     : (int)__ldg((const long long*)pinp + (size_t)k * (size_t)n + nn);
        cnt++;
        const float4 fv = reinterpret_cast<const float4*>(features)[(size_t)j * 16 + c4];
        const float4 wv = reinterpret_cast<const float4*>(weight)[k * 16 + c4];
        acc.x = fmaf(fv.x, wv.x, acc.x);
        acc.y = fmaf(fv.y, wv.y, acc.y);
        acc.z = fmaf(fv.z, wv.z, acc.z);
        acc.w = fmaf(fv.w, wv.w, acc.w);
    }
    // self tap (k = 13)
    {
        const float4 fv = reinterpret_cast<const float4*>(features)[(size_t)nn * 16 + c4];
        const float4 wv = reinterpret_cast<const float4*>(weight)[SELF_K * 16 + c4];
        acc.x = fmaf(fv.x, wv.x, acc.x);
        acc.y = fmaf(fv.y, wv.y, acc.y);
        acc.z = fmaf(fv.z, wv.z, acc.z);
        acc.w = fmaf(fv.w, wv.w, acc.w);
    }
    while (bhi) {
        const int kb = __ffs(bhi) - 1;
        bhi &= bhi - 1;
        const int k = kb + SELF_K + 1;
        int j;
        if      (cnt == 0) j = (int)info.y;
        else if (cnt == 1) j = (int)info.z;
        else if (cnt == 2) j = (int)info.w;
        else j = pw4 ? __ldg(p32 + (size_t)k * (size_t)n + nn)
                     : (int)__ldg((const long long*)pinp + (size_t)k * (size_t)n + nn);
        cnt++;
        const float4 fv = reinterpret_cast<const float4*>(features)[(size_t)j * 16 + c4];
        const float4 wv = reinterpret_cast<const float4*>(weight)[k * 16 + c4];
        acc.x = fmaf(fv.x, wv.x, acc.x);
        acc.y = fmaf(fv.y, wv.y, acc.y);
        acc.z = fmaf(fv.z, wv.z, acc.z);
        acc.w = fmaf(fv.w, wv.w, acc.w);
    }
}

// ---------------- main kernel: 2 rows/thread, no smem/barriers/atomics ----------------
__global__ __launch_bounds__(THREADS)
void spdwconv_kernel(const float* __restrict__ features,
                     const float* __restrict__ weight,   // [27*64], L1-resident
                     const float* __restrict__ bias,     // [64]
                     const void* __restrict__ pinp,      // pair_in (overflow only)
                     float* __restrict__ out,
                     int n)
{
    const int* p32 = (const int*)pinp;
    const bool pw4 = (__ldg(p32 + (size_t)SELF_K * (size_t)n + 1) == 1) &&
                     (__ldg(p32 + (size_t)SELF_K * (size_t)n + 2) == 2);

    const int t   = threadIdx.x;
    const int r   = t >> 4;       // 0..15
    const int c4  = t & 15;       // float4 channel group
    const int n0  = blockIdx.x * TILE;
    const int nnA = n0 + r;
    const int nnB = n0 + 16 + r;
    const bool vA = nnA < n;
    const bool vB = nnB < n;
    if (!vA) return;              // rows are contiguous: !vA implies !vB

    // Issue both info loads back-to-back (independent chains, MLP=2).
    const uint4 infoA = g_info[nnA];
    const uint4 infoB = vB ? g_info[nnB] : make_uint4(0, 0, 0, 0);

    const float4 bv = reinterpret_cast<const float4*>(bias)[c4];
    float4 accA = bv;
    float4 accB = bv;

    row_taps(accA, infoA, nnA, features, weight, c4, p32, pinp, pw4, n);
    if (vB) row_taps(accB, infoB, nnB, features, weight, c4, p32, pinp, pw4, n);

    __stcs(reinterpret_cast<float4*>(out) + (size_t)nnA * 16 + c4, accA);
    if (vB) __stcs(reinterpret_cast<float4*>(out) + (size_t)nnB * 16 + c4, accB);
}

extern "C" void kernel_launch(void* const* d_in, const int* in_sizes, int n_in,
                              void* d_out, int out_size)
{
    // Inputs in metadata order: features, weight, bias, pair_in, pair_out,
    // pair_mask. Identify by element count; the three 27*N arrays keep their
    // metadata order (pair_in, pair_out, pair_mask).
    int fi = -1, wi = -1, bi = -1;
    int big[3], nbig = 0;
    long long maxc = -1;
    for (int i = 0; i < n_in; i++)
        if ((long long)in_sizes[i] > maxc) { maxc = in_sizes[i]; fi = i; }
    for (int i = 0; i < n_in; i++) {
        if (i == fi) continue;
        if (in_sizes[i] == 64) bi = i;
        else if (in_sizes[i] == KTAPS * CCH) wi = i;
        else if (nbig < 3) big[nbig++] = i;
    }
    const float* features = (const float*)d_in[fi];
    const float* weight   = (const float*)d_in[wi];
    const float* bias     = (const float*)d_in[bi];
    const void*  pinp     = d_in[big[0]];   // pair_in
    // big[1] = pair_out (unused: scatter target == row under mask)
    const void*  maskp    = d_in[big[2]];   // pair_mask
    float* out = (float*)d_out;

    const int n = in_sizes[fi] / CCH;

    kbits<<<(n + 255) / 256, 256>>>(maskp, pinp, n);

    const int grid = (n + TILE - 1) / TILE;
    spdwconv_kernel<<<grid, THREADS>>>(features, weight, bias, pinp, out, n);
}